// round 7
// baseline (speedup 1.0000x reference)
#include <cuda_runtime.h>
#include <math.h>

typedef unsigned long long ULL;

// ---------------- static scratch (no allocations allowed) ----------------
__device__ __align__(16) float g_v[2 * 1024 * 64];      // vertex feats [B,N,64]
__device__ __align__(16) float g_f[2 * 2048 * 64];      // face feats   [B,F,64]
__device__ __align__(16) float g_X[2 * 4096 * 16];      // x buffer
__device__ __align__(16) float g_Y[2 * 8192 * 16];      // y buffer
__device__ __align__(16) float g_part[4194304];         // split-K partials (16 MB)
__device__ float g_sp[256 * 64];
__device__ float g_sq[256 * 64];
__device__ float g_pool[2 * 64];

// ---------------- helpers ----------------
__device__ __forceinline__ float elu1(float x) { return x > 0.f ? x : expm1f(x); }

__device__ __forceinline__ ULL pk2(float s) {
    ULL r; asm("mov.b64 %0, {%1, %1};" : "=l"(r) : "f"(s)); return r;
}
__device__ __forceinline__ void fma2(ULL& d, ULL a, ULL b) {
    asm("fma.rn.f32x2 %0, %1, %2, %0;" : "+l"(d) : "l"(a), "l"(b));
}
__device__ __forceinline__ void cpa16(unsigned dst, const float* src) {
    asm volatile("cp.async.cg.shared.global [%0], [%1], 16;" :: "r"(dst), "l"(src));
}

// ---------------- init: v = inp@Win + b, fused elu-stats partials ----------------
__global__ void __launch_bounds__(256) k_init_v(const float* __restrict__ inp,
                                                const float* __restrict__ Win,
                                                const float* __restrict__ bin) {
    __shared__ float ss[256], qq[256];
    int tid = threadIdx.x, ch = tid & 63;
    float b = bin[ch], w0 = Win[ch], w1 = Win[64 + ch], w2 = Win[128 + ch];
    float s = 0.f, q = 0.f;
#pragma unroll
    for (int e = 0; e < 2; e++) {
        int idx = e * 65536 + blockIdx.x * 256 + tid;    // 256 blocks cover 131072
        int r = idx >> 6;
        float acc = fmaf(inp[r * 3 + 2], w2, fmaf(inp[r * 3 + 1], w1, fmaf(inp[r * 3], w0, b)));
        g_v[idx] = acc;
        float x = elu1(acc); s += x; q += x * x;
    }
    ss[tid] = s; qq[tid] = q;
    __syncthreads();
    if (tid < 64) {
#pragma unroll
        for (int j = 1; j < 4; j++) { s += ss[tid + 64 * j]; q += qq[tid + 64 * j]; }
        g_sp[blockIdx.x * 64 + tid] = s;
        g_sq[blockIdx.x * 64 + tid] = q;
    }
}

__global__ void k_zero(float* __restrict__ p, int n) {
    int i = blockIdx.x * 256 + threadIdx.x;
    if (i < n) p[i] = 0.f;
}

// ---------------- elu -> BN -> 64x64 linear -> elu, BN coefs fused in ----------------
__global__ void __launch_bounds__(256) k_xform(const float* __restrict__ src,
                                               const float* __restrict__ W,
                                               const float* __restrict__ bias,
                                               const float* __restrict__ gamma,
                                               const float* __restrict__ beta,
                                               float invc, int nblk,
                                               float* __restrict__ dst) {
    __shared__ float Ws[64 * 64];
    __shared__ float ts[16][64];
    __shared__ float sa[64], sc[64];
    __shared__ float rs[256], rq[256];
    int tid = threadIdx.x;
    int ch = tid & 63, grp = tid >> 6;

    float s = 0.f, q = 0.f;
    for (int i = grp; i < nblk; i += 4) { s += g_sp[i * 64 + ch]; q += g_sq[i * 64 + ch]; }
    rs[tid] = s; rq[tid] = q;
    for (int i = tid; i < 4096; i += 256) Ws[i] = W[i];
    __syncthreads();
    if (tid < 64) {
#pragma unroll
        for (int j = 1; j < 4; j++) { s += rs[tid + 64 * j]; q += rq[tid + 64 * j]; }
        float m = s * invc;
        float var = q * invc - m * m;
        float a = gamma[tid] * rsqrtf(var + 1e-5f);
        sa[tid] = a;
        sc[tid] = beta[tid] - m * a;
    }
    __syncthreads();

    float a = sa[ch], c = sc[ch], bb = bias[ch];
    size_t base = (size_t)blockIdx.x * 1024;             // 16 rows * 64
#pragma unroll
    for (int j = 0; j < 4; j++) {
        float x = elu1(src[base + tid + 256 * j]);
        ts[grp + 4 * j][ch] = fmaf(x, a, c);
    }
    __syncthreads();
    float acc[4] = {bb, bb, bb, bb};
#pragma unroll
    for (int k = 0; k < 64; k++) {
        float w = Ws[k * 64 + ch];
#pragma unroll
        for (int j = 0; j < 4; j++) acc[j] = fmaf(ts[grp + 4 * j][k], w, acc[j]);
    }
#pragma unroll
    for (int j = 0; j < 4; j++) dst[base + tid + 256 * j] = elu1(acc[j]);
}

// ---------------- skinny GEMM: part[slice] = D[256-row tile, k-range] @ X ----------------
// grid (KS, M/256, B), block 128, 3 CTAs/SM (68KB dyn smem). Chunks of 32 k
// (128B/row): cpa16 staging into 128B-stride rows with 16B XOR swizzle
// (granule = g ^ (r&7)) -> aligned stores, conflict-free LDS.128 reads.
// Thread owns 8 rows (rl+32j) x 4 cols (q*4..+3). X per-k LDS.128 broadcast.
// Uneven split-K: slice s covers chunk-cols [NC*s/KS, NC*(s+1)/KS).
__global__ void __launch_bounds__(128) k_gemm(const float* __restrict__ D,
                                              const float* __restrict__ X,
                                              float* __restrict__ part,
                                              int M, int K, int NC, int KS) {
    extern __shared__ __align__(16) float smem[];
    float* Ds = smem;                                    // 2 x 256 x 32
    float* Xs = smem + 16384;                            // 2 x 32 x 16
    const int tid = threadIdx.x;
    const int s = blockIdx.x, mt = blockIdx.y, b = blockIdx.z;
    const int c0 = (NC * s) / KS;
    const int nch = (NC * (s + 1)) / KS - c0;
    const float* Dg = D + ((size_t)b * M + (size_t)mt * 256) * K + c0 * 32;
    const float* Xg = X + ((size_t)b * K + (size_t)c0 * 32) * 16;

    unsigned dsb = (unsigned)__cvta_generic_to_shared(Ds);
    unsigned xsb = (unsigned)__cvta_generic_to_shared(Xs);

    const int g = tid & 7, rb = tid >> 3;                // staging granule / row base

    auto issue = [&](int c, int buf) {
        unsigned dd = dsb + buf * 32768u;
        const float* src = Dg + c * 32 + g * 4;
#pragma unroll
        for (int j = 0; j < 16; j++) {
            int r = rb + 16 * j;
            cpa16(dd + (unsigned)(r * 128 + 16 * (g ^ (r & 7))), src + (size_t)r * K);
        }
        cpa16(xsb + buf * 2048u + tid * 16u, Xg + c * 512 + tid * 4);
        asm volatile("cp.async.commit_group;");
    };

    ULL acc[8][2];
#pragma unroll
    for (int j = 0; j < 8; j++) { acc[j][0] = 0ULL; acc[j][1] = 0ULL; }

    const int q = tid & 3, rl = tid >> 2;                // compute: col group, row lane

    issue(0, 0);

    for (int c = 0; c < nch; c++) {
        if (c + 1 < nch) {
            issue(c + 1, (c + 1) & 1);
            asm volatile("cp.async.wait_group 1;");
        } else {
            asm volatile("cp.async.wait_group 0;");
        }
        __syncthreads();
        const float* dsm = Ds + (c & 1) * 8192;
        const float* xsm = Xs + (c & 1) * 512;
#pragma unroll
        for (int kq = 0; kq < 8; kq++) {
            ulonglong2 xv[4];
#pragma unroll
            for (int dk = 0; dk < 4; dk++)
                xv[dk] = *(const ulonglong2*)&xsm[(kq * 4 + dk) * 16 + q * 4];
#pragma unroll
            for (int j = 0; j < 8; j++) {
                int r = rl + 32 * j;
                float4 d = *(const float4*)&dsm[r * 32 + 4 * (kq ^ (r & 7))];
                ULL w0 = pk2(d.x), w1 = pk2(d.y), w2 = pk2(d.z), w3 = pk2(d.w);
                fma2(acc[j][0], w0, xv[0].x); fma2(acc[j][1], w0, xv[0].y);
                fma2(acc[j][0], w1, xv[1].x); fma2(acc[j][1], w1, xv[1].y);
                fma2(acc[j][0], w2, xv[2].x); fma2(acc[j][1], w2, xv[2].y);
                fma2(acc[j][0], w3, xv[3].x); fma2(acc[j][1], w3, xv[3].y);
            }
        }
        __syncthreads();
    }

    size_t obase = ((size_t)s * gridDim.z + b) * M + (size_t)mt * 256;
#pragma unroll
    for (int j = 0; j < 8; j++) {
        ulonglong2 t; t.x = acc[j][0]; t.y = acc[j][1];
        *(ulonglong2*)(part + (obase + rl + 32 * j) * 16 + q * 4) = t;
    }
}

// ---------------- split-K reduce + fused elu-stats partials ----------------
__global__ void __launch_bounds__(256) k_reduce(float4* __restrict__ out,
                                                const float4* __restrict__ part,
                                                int n4, int ksplit) {
    __shared__ float ss[256 * 4], qq[256 * 4];
    int tid = threadIdx.x;
    int i = blockIdx.x * 256 + tid;
    float4 a = out[i];
    for (int s = 0; s < ksplit; s++) {
        float4 p = part[(size_t)s * n4 + i];
        a.x += p.x; a.y += p.y; a.z += p.z; a.w += p.w;
    }
    out[i] = a;
    float e0 = elu1(a.x), e1 = elu1(a.y), e2 = elu1(a.z), e3 = elu1(a.w);
    ss[tid * 4 + 0] = e0; qq[tid * 4 + 0] = e0 * e0;
    ss[tid * 4 + 1] = e1; qq[tid * 4 + 1] = e1 * e1;
    ss[tid * 4 + 2] = e2; qq[tid * 4 + 2] = e2 * e2;
    ss[tid * 4 + 3] = e3; qq[tid * 4 + 3] = e3 * e3;
    __syncthreads();
    if (tid < 64) {
        int g = tid >> 2, e = tid & 3;                  // channel = 4*g + e
        float s = 0.f, q = 0.f;
#pragma unroll
        for (int m = 0; m < 16; m++) {
            int t = g + 16 * m;
            s += ss[t * 4 + e]; q += qq[t * 4 + e];
        }
        g_sp[blockIdx.x * 64 + tid] = s;
        g_sq[blockIdx.x * 64 + tid] = q;
    }
}

// ---------------- epilogue ----------------
__global__ void k_pool(const float* __restrict__ t, const float* __restrict__ mask) {
    __shared__ float ss[256], ms[256];
    int b = blockIdx.x;
    int ch = threadIdx.x & 63, g = threadIdx.x >> 6;
    float s = 0.f, m = 0.f;
    for (int n = g; n < 1024; n += 4) {
        float mv = mask[b * 1024 + n];
        s += t[((size_t)b * 1024 + n) * 64 + ch] * mv;
        m += mv;
    }
    ss[threadIdx.x] = s; ms[threadIdx.x] = m;
    __syncthreads();
    if (g == 0) {
#pragma unroll
        for (int j = 1; j < 4; j++) { s += ss[ch + 64 * j]; m += ms[ch + 64 * j]; }
        g_pool[b * 64 + ch] = s / m;
    }
}

__global__ void k_head(const float* __restrict__ Wfc, const float* __restrict__ bfc,
                       float* __restrict__ out) {
    __shared__ float lg[2][10];
    int tid = threadIdx.x;
    if (tid < 20) {
        int b = tid / 10, j = tid % 10;
        float acc = bfc[j];
        for (int ch = 0; ch < 64; ch++) acc = fmaf(g_pool[b * 64 + ch], Wfc[ch * 10 + j], acc);
        lg[b][j] = acc;
    }
    __syncthreads();
    if (tid < 20) {
        int b = tid / 10, j = tid % 10;
        float mx = -1e30f;
        for (int t = 0; t < 10; t++) mx = fmaxf(mx, lg[b][t]);
        float se = 0.f;
        for (int t = 0; t < 10; t++) se += expf(lg[b][t] - mx);
        out[b * 10 + j] = lg[b][j] - mx - logf(se);
    }
}

// ---------------- launcher ----------------
extern "C" void kernel_launch(void* const* d_in, const int* in_sizes, int n_in,
                              void* d_out, int out_size) {
    const float* inp  = (const float*)d_in[0];
    const float* Di   = (const float*)d_in[1];
    const float* DiA  = (const float*)d_in[2];
    const float* mask = (const float*)d_in[3];
    const float* W_in = (const float*)d_in[4];
    const float* b_in = (const float*)d_in[5];
    const float* rnW0 = (const float*)d_in[6];
    const float* rnb0 = (const float*)d_in[7];
    const float* rng0 = (const float*)d_in[8];
    const float* rnbe0= (const float*)d_in[9];
    const float* rnW1 = (const float*)d_in[10];
    const float* rnb1 = (const float*)d_in[11];
    const float* rng1 = (const float*)d_in[12];
    const float* rnbe1= (const float*)d_in[13];
    const float* bn2g = (const float*)d_in[14];
    const float* bn2b = (const float*)d_in[15];
    const float* W2   = (const float*)d_in[16];
    const float* b2   = (const float*)d_in[17];
    const float* Wfc  = (const float*)d_in[18];
    const float* bfc  = (const float*)d_in[19];
    float* out = (float*)d_out;

    float *v, *f, *X, *Y, *part;
    cudaGetSymbolAddress((void**)&v, g_v);
    cudaGetSymbolAddress((void**)&f, g_f);
    cudaGetSymbolAddress((void**)&X, g_X);
    cudaGetSymbolAddress((void**)&Y, g_Y);
    cudaGetSymbolAddress((void**)&part, g_part);

    const int SMEM = (16384 + 1024) * 4;                 // 68 KB dynamic
    cudaFuncSetAttribute(k_gemm, cudaFuncAttributeMaxDynamicSharedMemorySize, SMEM);

    k_init_v<<<256, 256>>>(inp, W_in, b_in);             // #1  (v + bn stats partials)
    k_zero<<<1024, 256>>>(f, 2 * 2048 * 64);             // #2

    int nblk_v = 256;
    for (int i = 0; i < 5; i++) {
        // vertex -> face
        k_xform<<<128, 256>>>(v, rnW0 + i * 4096, rnb0 + i * 64,
                              rng0 + i * 64, rnbe0 + i * 64,
                              1.f / 2048.f, nblk_v, X);  // #3 (gemm is #4 for ncu)
        k_gemm<<<dim3(7, 32, 2), 128, SMEM>>>(Di, X, part, 8192, 4096, 128, 7);
        k_reduce<<<256, 256>>>((float4*)f, (const float4*)part, 65536, 7);
        // face -> vertex
        k_xform<<<256, 256>>>(f, rnW1 + i * 4096, rnb1 + i * 64,
                              rng1 + i * 64, rnbe1 + i * 64,
                              1.f / 4096.f, 256, Y);
        k_gemm<<<dim3(14, 16, 2), 128, SMEM>>>(DiA, Y, part, 4096, 8192, 256, 14);
        k_reduce<<<128, 256>>>((float4*)v, (const float4*)part, 32768, 14);
        nblk_v = 128;
    }

    // epilogue
    k_xform<<<128, 256>>>(v, W2, b2, bn2g, bn2b, 1.f / 2048.f, nblk_v, Y);
    k_pool<<<2, 256>>>(Y, mask);
    k_head<<<1, 32>>>(Wfc, bfc, out);
}

// round 8
// speedup vs baseline: 1.3781x; 1.3781x over previous
#include <cuda_runtime.h>
#include <math.h>

typedef unsigned long long ULL;

// ---------------- static scratch (no allocations allowed) ----------------
__device__ __align__(16) float g_v[2 * 1024 * 64];      // vertex feats [B,N,64]
__device__ __align__(16) float g_f[2 * 2048 * 64];      // face feats   [B,F,64]
__device__ __align__(16) float g_X[2 * 4096 * 16];      // x buffer
__device__ __align__(16) float g_Y[2 * 8192 * 16];      // y buffer
__device__ __align__(16) float g_part[4194304];         // split-K partials (16 MB)
__device__ float g_sp[256 * 64];
__device__ float g_sq[256 * 64];
__device__ float g_pool[2 * 64];

// ---------------- helpers ----------------
__device__ __forceinline__ float elu1(float x) { return x > 0.f ? x : expm1f(x); }

__device__ __forceinline__ ULL pk2(float s) {
    ULL r; asm("mov.b64 %0, {%1, %1};" : "=l"(r) : "f"(s)); return r;
}
__device__ __forceinline__ void fma2(ULL& d, ULL a, ULL b) {
    asm("fma.rn.f32x2 %0, %1, %2, %0;" : "+l"(d) : "l"(a), "l"(b));
}
__device__ __forceinline__ void cpa16(unsigned dst, const float* src) {
    asm volatile("cp.async.cg.shared.global [%0], [%1], 16;" :: "r"(dst), "l"(src));
}

// ---------------- init: v = inp@Win + b, fused elu-stats partials ----------------
__global__ void __launch_bounds__(256) k_init_v(const float* __restrict__ inp,
                                                const float* __restrict__ Win,
                                                const float* __restrict__ bin) {
    __shared__ float ss[256], qq[256];
    int tid = threadIdx.x, ch = tid & 63;
    float b = bin[ch], w0 = Win[ch], w1 = Win[64 + ch], w2 = Win[128 + ch];
    float s = 0.f, q = 0.f;
#pragma unroll
    for (int e = 0; e < 2; e++) {
        int idx = e * 65536 + blockIdx.x * 256 + tid;    // 256 blocks cover 131072
        int r = idx >> 6;
        float acc = fmaf(inp[r * 3 + 2], w2, fmaf(inp[r * 3 + 1], w1, fmaf(inp[r * 3], w0, b)));
        g_v[idx] = acc;
        float x = elu1(acc); s += x; q += x * x;
    }
    ss[tid] = s; qq[tid] = q;
    __syncthreads();
    if (tid < 64) {
#pragma unroll
        for (int j = 1; j < 4; j++) { s += ss[tid + 64 * j]; q += qq[tid + 64 * j]; }
        g_sp[blockIdx.x * 64 + tid] = s;
        g_sq[blockIdx.x * 64 + tid] = q;
    }
}

__global__ void k_zero(float* __restrict__ p, int n) {
    int i = blockIdx.x * 256 + threadIdx.x;
    if (i < n) p[i] = 0.f;
}

// ---------------- elu -> BN -> 64x64 linear -> elu, BN coefs fused in ----------------
__global__ void __launch_bounds__(256) k_xform(const float* __restrict__ src,
                                               const float* __restrict__ W,
                                               const float* __restrict__ bias,
                                               const float* __restrict__ gamma,
                                               const float* __restrict__ beta,
                                               float invc, int nblk,
                                               float* __restrict__ dst) {
    __shared__ float Ws[64 * 64];
    __shared__ float ts[16][64];
    __shared__ float sa[64], sc[64];
    __shared__ float rs[256], rq[256];
    int tid = threadIdx.x;
    int ch = tid & 63, grp = tid >> 6;

    float s = 0.f, q = 0.f;
    for (int i = grp; i < nblk; i += 4) { s += g_sp[i * 64 + ch]; q += g_sq[i * 64 + ch]; }
    rs[tid] = s; rq[tid] = q;
    for (int i = tid; i < 4096; i += 256) Ws[i] = W[i];
    __syncthreads();
    if (tid < 64) {
#pragma unroll
        for (int j = 1; j < 4; j++) { s += rs[tid + 64 * j]; q += rq[tid + 64 * j]; }
        float m = s * invc;
        float var = q * invc - m * m;
        float a = gamma[tid] * rsqrtf(var + 1e-5f);
        sa[tid] = a;
        sc[tid] = beta[tid] - m * a;
    }
    __syncthreads();

    float a = sa[ch], c = sc[ch], bb = bias[ch];
    size_t base = (size_t)blockIdx.x * 1024;             // 16 rows * 64
#pragma unroll
    for (int j = 0; j < 4; j++) {
        float x = elu1(src[base + tid + 256 * j]);
        ts[grp + 4 * j][ch] = fmaf(x, a, c);
    }
    __syncthreads();
    float acc[4] = {bb, bb, bb, bb};
#pragma unroll
    for (int k = 0; k < 64; k++) {
        float w = Ws[k * 64 + ch];
#pragma unroll
        for (int j = 0; j < 4; j++) acc[j] = fmaf(ts[grp + 4 * j][k], w, acc[j]);
    }
#pragma unroll
    for (int j = 0; j < 4; j++) dst[base + tid + 256 * j] = elu1(acc[j]);
}

// ---------------- skinny GEMM: part[slice] = D[128-row tile, k-range] @ X ----------------
// grid (KS, M/128, B), block 128, 36 KB dyn smem -> 6 CTAs/SM, single wave.
// 32-k chunks (128B/row), cpa16 staging with 16B XOR swizzle (granule g^(rb&7),
// per-thread constant). Reads: per kq one LDS.128 per row, granule kq^rl ->
// 8 distinct granules x 8 rows cover all 32 banks (conflict-free, q broadcast).
// Thread owns 4 rows (rl+32j) x 4 cols. Uneven split-K over 32-k chunk columns.
__global__ void __launch_bounds__(128) k_gemm(const float* __restrict__ D,
                                              const float* __restrict__ X,
                                              float* __restrict__ part,
                                              int M, int K, int NC, int KS) {
    extern __shared__ __align__(16) float smem[];
    float* Ds = smem;                                    // 2 x 128 x 32
    float* Xs = smem + 8192;                             // 2 x 32 x 16
    const int tid = threadIdx.x;
    const int s = blockIdx.x, mt = blockIdx.y, b = blockIdx.z;
    const int c0 = (NC * s) / KS;
    const int nch = (NC * (s + 1)) / KS - c0;
    const float* Dg = D + ((size_t)b * M + (size_t)mt * 128) * K + c0 * 32;
    const float* Xg = X + ((size_t)b * K + (size_t)c0 * 32) * 16;

    unsigned dsb = (unsigned)__cvta_generic_to_shared(Ds);
    unsigned xsb = (unsigned)__cvta_generic_to_shared(Xs);

    const int g = tid & 7, rb = tid >> 3;                // staging granule / row base
    const unsigned gsw = 16u * (unsigned)(g ^ (rb & 7)); // per-thread constant swizzle

    auto issue = [&](int c, int buf) {
        unsigned dd = dsb + buf * 16384u;
        const float* src = Dg + c * 32 + g * 4;
#pragma unroll
        for (int j = 0; j < 8; j++) {
            int r = rb + 16 * j;
            cpa16(dd + (unsigned)(r * 128) + gsw, src + (size_t)r * K);
        }
        cpa16(xsb + buf * 2048u + tid * 16u, Xg + c * 512 + tid * 4);
        asm volatile("cp.async.commit_group;");
    };

    ULL acc[4][2];
#pragma unroll
    for (int j = 0; j < 4; j++) { acc[j][0] = 0ULL; acc[j][1] = 0ULL; }

    const int q = tid & 3, rl = tid >> 2;                // compute: col group, row lane

    issue(0, 0);

    for (int c = 0; c < nch; c++) {
        if (c + 1 < nch) {
            issue(c + 1, (c + 1) & 1);
            asm volatile("cp.async.wait_group 1;");
        } else {
            asm volatile("cp.async.wait_group 0;");
        }
        __syncthreads();
        const float* dsm = Ds + (c & 1) * 4096;
        const float* xsm = Xs + (c & 1) * 512;
#pragma unroll
        for (int kq = 0; kq < 8; kq++) {
            ulonglong2 xv[4];
#pragma unroll
            for (int dk = 0; dk < 4; dk++)
                xv[dk] = *(const ulonglong2*)&xsm[(kq * 4 + dk) * 16 + q * 4];
#pragma unroll
            for (int j = 0; j < 4; j++) {
                int r = rl + 32 * j;
                float4 d = *(const float4*)&dsm[r * 32 + 4 * (kq ^ (r & 7))];
                ULL w0 = pk2(d.x), w1 = pk2(d.y), w2 = pk2(d.z), w3 = pk2(d.w);
                fma2(acc[j][0], w0, xv[0].x); fma2(acc[j][1], w0, xv[0].y);
                fma2(acc[j][0], w1, xv[1].x); fma2(acc[j][1], w1, xv[1].y);
                fma2(acc[j][0], w2, xv[2].x); fma2(acc[j][1], w2, xv[2].y);
                fma2(acc[j][0], w3, xv[3].x); fma2(acc[j][1], w3, xv[3].y);
            }
        }
        __syncthreads();
    }

    size_t obase = ((size_t)s * gridDim.z + b) * M + (size_t)mt * 128;
#pragma unroll
    for (int j = 0; j < 4; j++) {
        ulonglong2 t; t.x = acc[j][0]; t.y = acc[j][1];
        *(ulonglong2*)(part + (obase + rl + 32 * j) * 16 + q * 4) = t;
    }
}

// ---------------- split-K reduce + fused elu-stats partials ----------------
__global__ void __launch_bounds__(256) k_reduce(float4* __restrict__ out,
                                                const float4* __restrict__ part,
                                                int n4, int ksplit) {
    __shared__ float ss[256 * 4], qq[256 * 4];
    int tid = threadIdx.x;
    int i = blockIdx.x * 256 + tid;
    float4 a = out[i];
    for (int s = 0; s < ksplit; s++) {
        float4 p = part[(size_t)s * n4 + i];
        a.x += p.x; a.y += p.y; a.z += p.z; a.w += p.w;
    }
    out[i] = a;
    float e0 = elu1(a.x), e1 = elu1(a.y), e2 = elu1(a.z), e3 = elu1(a.w);
    ss[tid * 4 + 0] = e0; qq[tid * 4 + 0] = e0 * e0;
    ss[tid * 4 + 1] = e1; qq[tid * 4 + 1] = e1 * e1;
    ss[tid * 4 + 2] = e2; qq[tid * 4 + 2] = e2 * e2;
    ss[tid * 4 + 3] = e3; qq[tid * 4 + 3] = e3 * e3;
    __syncthreads();
    if (tid < 64) {
        int g = tid >> 2, e = tid & 3;                  // channel = 4*g + e
        float s = 0.f, q = 0.f;
#pragma unroll
        for (int m = 0; m < 16; m++) {
            int t = g + 16 * m;
            s += ss[t * 4 + e]; q += qq[t * 4 + e];
        }
        g_sp[blockIdx.x * 64 + tid] = s;
        g_sq[blockIdx.x * 64 + tid] = q;
    }
}

// ---------------- epilogue ----------------
__global__ void k_pool(const float* __restrict__ t, const float* __restrict__ mask) {
    __shared__ float ss[256], ms[256];
    int b = blockIdx.x;
    int ch = threadIdx.x & 63, g = threadIdx.x >> 6;
    float s = 0.f, m = 0.f;
    for (int n = g; n < 1024; n += 4) {
        float mv = mask[b * 1024 + n];
        s += t[((size_t)b * 1024 + n) * 64 + ch] * mv;
        m += mv;
    }
    ss[threadIdx.x] = s; ms[threadIdx.x] = m;
    __syncthreads();
    if (g == 0) {
#pragma unroll
        for (int j = 1; j < 4; j++) { s += ss[ch + 64 * j]; m += ms[ch + 64 * j]; }
        g_pool[b * 64 + ch] = s / m;
    }
}

__global__ void k_head(const float* __restrict__ Wfc, const float* __restrict__ bfc,
                       float* __restrict__ out) {
    __shared__ float lg[2][10];
    int tid = threadIdx.x;
    if (tid < 20) {
        int b = tid / 10, j = tid % 10;
        float acc = bfc[j];
        for (int ch = 0; ch < 64; ch++) acc = fmaf(g_pool[b * 64 + ch], Wfc[ch * 10 + j], acc);
        lg[b][j] = acc;
    }
    __syncthreads();
    if (tid < 20) {
        int b = tid / 10, j = tid % 10;
        float mx = -1e30f;
        for (int t = 0; t < 10; t++) mx = fmaxf(mx, lg[b][t]);
        float se = 0.f;
        for (int t = 0; t < 10; t++) se += expf(lg[b][t] - mx);
        out[b * 10 + j] = lg[b][j] - mx - logf(se);
    }
}

// ---------------- launcher ----------------
extern "C" void kernel_launch(void* const* d_in, const int* in_sizes, int n_in,
                              void* d_out, int out_size) {
    const float* inp  = (const float*)d_in[0];
    const float* Di   = (const float*)d_in[1];
    const float* DiA  = (const float*)d_in[2];
    const float* mask = (const float*)d_in[3];
    const float* W_in = (const float*)d_in[4];
    const float* b_in = (const float*)d_in[5];
    const float* rnW0 = (const float*)d_in[6];
    const float* rnb0 = (const float*)d_in[7];
    const float* rng0 = (const float*)d_in[8];
    const float* rnbe0= (const float*)d_in[9];
    const float* rnW1 = (const float*)d_in[10];
    const float* rnb1 = (const float*)d_in[11];
    const float* rng1 = (const float*)d_in[12];
    const float* rnbe1= (const float*)d_in[13];
    const float* bn2g = (const float*)d_in[14];
    const float* bn2b = (const float*)d_in[15];
    const float* W2   = (const float*)d_in[16];
    const float* b2   = (const float*)d_in[17];
    const float* Wfc  = (const float*)d_in[18];
    const float* bfc  = (const float*)d_in[19];
    float* out = (float*)d_out;

    float *v, *f, *X, *Y, *part;
    cudaGetSymbolAddress((void**)&v, g_v);
    cudaGetSymbolAddress((void**)&f, g_f);
    cudaGetSymbolAddress((void**)&X, g_X);
    cudaGetSymbolAddress((void**)&Y, g_Y);
    cudaGetSymbolAddress((void**)&part, g_part);

    const int SMEM = (8192 + 1024) * 4;                  // 36 KB dynamic
    cudaFuncSetAttribute(k_gemm, cudaFuncAttributeMaxDynamicSharedMemorySize, SMEM);

    k_init_v<<<256, 256>>>(inp, W_in, b_in);             // #1  (v + bn stats partials)
    k_zero<<<1024, 256>>>(f, 2 * 2048 * 64);             // #2

    int nblk_v = 256;
    for (int i = 0; i < 5; i++) {
        // vertex -> face
        k_xform<<<128, 256>>>(v, rnW0 + i * 4096, rnb0 + i * 64,
                              rng0 + i * 64, rnbe0 + i * 64,
                              1.f / 2048.f, nblk_v, X);  // #3 (gemm is #4 for ncu)
        k_gemm<<<dim3(6, 64, 2), 128, SMEM>>>(Di, X, part, 8192, 4096, 128, 6);
        k_reduce<<<256, 256>>>((float4*)f, (const float4*)part, 65536, 6);
        // face -> vertex
        k_xform<<<256, 256>>>(f, rnW1 + i * 4096, rnb1 + i * 64,
                              rng1 + i * 64, rnbe1 + i * 64,
                              1.f / 4096.f, 256, Y);
        k_gemm<<<dim3(12, 32, 2), 128, SMEM>>>(DiA, Y, part, 4096, 8192, 256, 12);
        k_reduce<<<128, 256>>>((float4*)v, (const float4*)part, 32768, 12);
        nblk_v = 128;
    }

    // epilogue
    k_xform<<<128, 256>>>(v, W2, b2, bn2g, bn2b, 1.f / 2048.f, nblk_v, Y);
    k_pool<<<2, 256>>>(Y, mask);
    k_head<<<1, 32>>>(Wfc, bfc, out);
}